// round 4
// baseline (speedup 1.0000x reference)
#include <cuda_runtime.h>

#define LSEQ 2048
#define DK   64
#define NH   8
#define NB   2
#define NBH  (NB*NH)
#define NT   256
#define TI   16
#define TJ   256      // phase-1 chunk width (cols)
#define TJ4  128      // phase-4 chunk height (j rows)

// K^T scratch: per bh, [DK][LSEQ]
__device__ float g_kt[(size_t)NBH * DK * LSEQ];

// smem layout (floats)
//  sS   : TI*LSEQ        = 32768
//  sAux : DK*TJ          = 16384   (K^T chunk / V chunk(8192) / reduce(1024))
//  sQ2  : TI*DK*2        =  2048   (Q pre-splatted into f32x2 pairs)
//  sRow : TI
#define SMEM_FLOATS (TI*LSEQ + DK*TJ + TI*DK*2 + TI)
#define SMEM_BYTES  (SMEM_FLOATS * sizeof(float))

#define FMA2(d,a,b,c) asm("fma.rn.f32x2 %0, %1, %2, %3;" : "=l"(d) : "l"(a), "l"(b), "l"(c))
#define ADD2(d,a,b)   asm("add.rn.f32x2 %0, %1, %2;"     : "=l"(d) : "l"(a), "l"(b))
#define SPLAT2(d,s)   asm("mov.b64 %0, {%1, %1};"        : "=l"(d) : "f"(s))
#define UNPK2(lo,hi,s) asm("mov.b64 {%0, %1}, %2;"       : "=f"(lo), "=f"(hi) : "l"(s))

// ---------------------------------------------------------------------------
// prep: transpose K[bh][j][kk] -> g_kt[bh][kk][j].  grid = NBH*32, 256 thr.
// ---------------------------------------------------------------------------
__global__ void prep_kernel(const float* __restrict__ K)
{
    __shared__ float sT[64 * 65];
    const int bh = blockIdx.x >> 5;
    const int jt = blockIdx.x & 31;          // 64-row j tile
    const int t  = threadIdx.x;
    const float* Kb = K + ((size_t)bh * LSEQ + jt * 64) * DK;

    #pragma unroll
    for (int it = 0; it < 4; it++) {
        int q   = t + it * NT;               // 0..1023 float4s
        int row = q >> 4;                    // j within tile
        int c4  = (q & 15) << 2;             // kk
        float4 v = *(const float4*)(Kb + (size_t)row * DK + c4);
        sT[(c4 + 0) * 65 + row] = v.x;
        sT[(c4 + 1) * 65 + row] = v.y;
        sT[(c4 + 2) * 65 + row] = v.z;
        sT[(c4 + 3) * 65 + row] = v.w;
    }
    __syncthreads();
    float* KTb = g_kt + (size_t)bh * DK * LSEQ + jt * 64;
    #pragma unroll
    for (int it = 0; it < 4; it++) {
        int q  = t + it * NT;
        int kk = q >> 4;
        int j4 = (q & 15) << 2;
        float4 v;
        v.x = sT[kk * 65 + j4 + 0];
        v.y = sT[kk * 65 + j4 + 1];
        v.z = sT[kk * 65 + j4 + 2];
        v.w = sT[kk * 65 + j4 + 3];
        *(float4*)(KTb + (size_t)kk * LSEQ + j4) = v;
    }
}

// ---------------------------------------------------------------------------
// Main fused kernel. grid = (LSEQ/TI, NBH), 256 threads, ~200KB smem.
// ---------------------------------------------------------------------------
__global__ __launch_bounds__(NT, 1)
void raa_kernel(const float* __restrict__ Q, const float* __restrict__ V,
                const unsigned char* __restrict__ M,
                const float* __restrict__ TS, const float* __restrict__ LS,
                float* __restrict__ Osum, float* __restrict__ Pout)
{
    extern __shared__ float sm[];
    float* sS   = sm;
    float* sAux = sS + TI * LSEQ;
    float* sQ2  = sAux + DK * TJ;
    float* sRow = sQ2 + TI * DK * 2;
    __shared__ int sFlag;

    const int t  = threadIdx.x;
    const int bh = blockIdx.y;
    const int b  = bh >> 3;
    const int i0 = blockIdx.x * TI;
    const float scale = 0.07216878364870323f;   // 1/sqrt(3*64)

    const float* Qb  = Q  + (size_t)bh * LSEQ * DK;
    const float* Vb  = V  + (size_t)bh * LSEQ * DK;
    const float* TSb = TS + ((size_t)bh * LSEQ + i0) * LSEQ;
    const float* LSb = LS + ((size_t)bh * LSEQ + i0) * LSEQ;
    const size_t moff = ((size_t)b * LSEQ + i0) * LSEQ;
    const float* KTb = g_kt + (size_t)bh * DK * LSEQ;

    // ---- mask dtype probe (thread 0) + Q splat load ----
    if (t == 0) {
        const int*   mi = (const int*)M;
        const float* mf = (const float*)M;
        bool okI = true, okF = true;
        for (int i = 0; i < 64; i++) {
            int   vi = mi[i];
            float vf = mf[i];
            if (vi != 0 && vi != 1)       okI = false;
            if (vf != 0.f && vf != 1.f)   okF = false;
        }
        sFlag = okI ? 1 : (okF ? 2 : 0);
    }
    {
        float4 qv = ((const float4*)(Qb + (size_t)i0 * DK))[t];
        int e = t * 4, row = e >> 6, kk = e & 63;
        float* d = sQ2 + ((size_t)row * DK + kk) * 2;
        d[0]=qv.x; d[1]=qv.x; d[2]=qv.y; d[3]=qv.y;
        d[4]=qv.z; d[5]=qv.z; d[6]=qv.w; d[7]=qv.w;
    }
    __syncthreads();
    const int flag = sFlag;

    // ---- Phase 1: S = (QK^T + tree + leaf)*scale, masked ----
    const int cq  = t & 63;         // col quad index (4 cols)
    const int ra  = (t >> 6) * 4;   // first of 4 rows
    const int jgq = cq * 4;

    for (int jc = 0; jc < LSEQ; jc += TJ) {
        __syncthreads();
        #pragma unroll
        for (int it = 0; it < 16; it++) {
            int idx = t + it * NT;              // 0..4095 float4s
            int kk  = idx >> 6;
            int c4  = (idx & 63) << 2;
            *(float4*)(sAux + kk * TJ + c4) =
                *(const float4*)(KTb + (size_t)kk * LSEQ + jc + c4);
        }
        // prefetch bias + mask for this thread's 4x4 tile
        const int jg = jc + jgq;
        float4 bias[4];
        unsigned mb = 0;
        #pragma unroll
        for (int r = 0; r < 4; r++) {
            float4 t4 = *(const float4*)(TSb + (size_t)(ra + r) * LSEQ + jg);
            float4 l4 = *(const float4*)(LSb + (size_t)(ra + r) * LSEQ + jg);
            bias[r].x = t4.x + l4.x; bias[r].y = t4.y + l4.y;
            bias[r].z = t4.z + l4.z; bias[r].w = t4.w + l4.w;
            unsigned m4;
            size_t eo = moff + (size_t)(ra + r) * LSEQ + jg;
            if (flag == 0) {
                unsigned w = *(const unsigned*)(M + eo);
                m4 = (w & 1u) | ((w >> 7) & 2u) | ((w >> 14) & 4u) | ((w >> 21) & 8u);
            } else if (flag == 1) {
                int4 w = *(const int4*)((const int*)M + eo);
                m4 = (w.x?1u:0u) | (w.y?2u:0u) | (w.z?4u:0u) | (w.w?8u:0u);
            } else {
                float4 w = *(const float4*)((const float*)M + eo);
                m4 = (w.x!=0.f?1u:0u) | (w.y!=0.f?2u:0u) | (w.z!=0.f?4u:0u) | (w.w!=0.f?8u:0u);
            }
            mb |= m4 << (r * 4);
        }
        __syncthreads();

        unsigned long long a0[4] = {0,0,0,0}, a1[4] = {0,0,0,0};
        #pragma unroll 8
        for (int kk = 0; kk < DK; kk += 2) {
            ulonglong2 kv0 = *(const ulonglong2*)(sAux + kk * TJ + jgq);
            ulonglong2 kv1 = *(const ulonglong2*)(sAux + (kk + 1) * TJ + jgq);
            #pragma unroll
            for (int r = 0; r < 4; r++) {
                ulonglong2 qp = *(const ulonglong2*)(sQ2 + ((size_t)(ra + r) * DK + kk) * 2);
                FMA2(a0[r], qp.x, kv0.x, a0[r]);
                FMA2(a1[r], qp.x, kv0.y, a1[r]);
                FMA2(a0[r], qp.y, kv1.x, a0[r]);
                FMA2(a1[r], qp.y, kv1.y, a1[r]);
            }
        }
        #pragma unroll
        for (int r = 0; r < 4; r++) {
            float lx, ly, hx, hy;
            UNPK2(lx, ly, a0[r]);
            UNPK2(hx, hy, a1[r]);
            float4 s;
            s.x = (mb >> (r*4)     & 1) ? -1e9f : (lx + bias[r].x) * scale;
            s.y = (mb >> (r*4 + 1) & 1) ? -1e9f : (ly + bias[r].y) * scale;
            s.z = (mb >> (r*4 + 2) & 1) ? -1e9f : (hx + bias[r].z) * scale;
            s.w = (mb >> (r*4 + 3) & 1) ? -1e9f : (hy + bias[r].w) * scale;
            *(float4*)(sS + (size_t)(ra + r) * LSEQ + jg) = s;
        }
    }
    __syncthreads();

    // ---- Phase 2: per-row max / exp / sum (16 threads per row, float4) ----
    {
        const int row = t >> 4;
        const int l16 = t & 15;
        float* sSr = sS + (size_t)row * LSEQ;
        float m = -3.4e38f;
        for (int k = l16; k < LSEQ/4; k += 16) {
            float4 v = ((const float4*)sSr)[k];
            m = fmaxf(m, fmaxf(fmaxf(v.x, v.y), fmaxf(v.z, v.w)));
        }
        #pragma unroll
        for (int k = 8; k >= 1; k >>= 1)
            m = fmaxf(m, __shfl_xor_sync(0xffffffffu, m, k));
        float sum = 0.f;
        for (int k = l16; k < LSEQ/4; k += 16) {
            float4 v = ((const float4*)sSr)[k];
            v.x = __expf(v.x - m); v.y = __expf(v.y - m);
            v.z = __expf(v.z - m); v.w = __expf(v.w - m);
            ((float4*)sSr)[k] = v;
            sum += (v.x + v.y) + (v.z + v.w);
        }
        #pragma unroll
        for (int k = 8; k >= 1; k >>= 1)
            sum += __shfl_xor_sync(0xffffffffu, sum, k);
        if (l16 == 0) sRow[row] = 1.0f / sum;
    }
    __syncthreads();

    // ---- Phase 3: normalize in smem + stream p_attn to gmem ----
    {
        float* Pb = Pout + ((size_t)bh * LSEQ + i0) * LSEQ;
        #pragma unroll
        for (int it = 0; it < (TI * LSEQ / 4) / NT; it++) {   // 32 iters
            int fidx = (t + it * NT) * 4;
            int r = fidx >> 11;
            float rinv = sRow[r];
            float4 p = *(float4*)(sS + fidx);
            p.x *= rinv; p.y *= rinv; p.z *= rinv; p.w *= rinv;
            *(float4*)(sS + fidx) = p;
            *(float4*)(Pb + fidx) = p;
        }
    }

    // ---- Phase 4: O = P V  (j split in halves; f32x2 dim pairs) ----
    const int prow = (t >> 3) & 15;   // output row
    const int oct  = t & 7;           // dim octet: dims oct*8 .. +7
    const int jh   = t >> 7;          // j-half
    unsigned long long accA0 = 0, accA1 = 0, accB0 = 0, accB1 = 0;

    for (int jc = 0; jc < LSEQ; jc += TJ4) {
        __syncthreads();
        #pragma unroll
        for (int it = 0; it < 8; it++) {
            int idx = t + it * NT;    // 0..2047 float4s of V chunk
            *(float4*)(sAux + idx * 4) =
                *(const float4*)(Vb + (size_t)jc * DK + idx * 4);
        }
        __syncthreads();
        const float* pr  = sS + (size_t)prow * LSEQ + jc + jh * 64;
        const float* vb0 = sAux + jh * 64 * DK + oct * 8;
        #pragma unroll 4
        for (int j4 = 0; j4 < 64; j4 += 4) {
            float4 p = *(const float4*)(pr + j4);
            #pragma unroll
            for (int u = 0; u < 4; u++) {
                float pv = (u == 0) ? p.x : (u == 1) ? p.y : (u == 2) ? p.z : p.w;
                unsigned long long ps;
                SPLAT2(ps, pv);
                const ulonglong2* v = (const ulonglong2*)(vb0 + (size_t)(j4 + u) * DK);
                ulonglong2 vA = v[0];
                ulonglong2 vB = v[1];
                FMA2(accA0, ps, vA.x, accA0);
                FMA2(accA1, ps, vA.y, accA1);
                FMA2(accB0, ps, vB.x, accB0);
                FMA2(accB1, ps, vB.y, accB1);
            }
        }
    }
    // cross-half reduce via sAux
    __syncthreads();
    if (jh == 1) {
        unsigned long long* red = (unsigned long long*)sAux + (size_t)(t - 128) * 4;
        red[0] = accA0; red[1] = accA1; red[2] = accB0; red[3] = accB1;
    }
    __syncthreads();
    if (jh == 0) {
        const unsigned long long* red = (const unsigned long long*)sAux + (size_t)t * 4;
        ADD2(accA0, accA0, red[0]);
        ADD2(accA1, accA1, red[1]);
        ADD2(accB0, accB0, red[2]);
        ADD2(accB1, accB1, red[3]);
        float4 o0, o1;
        UNPK2(o0.x, o0.y, accA0); UNPK2(o0.z, o0.w, accA1);
        UNPK2(o1.x, o1.y, accB0); UNPK2(o1.z, o1.w, accB1);
        float* Ob = Osum + ((size_t)bh * LSEQ + i0 + prow) * DK + oct * 8;
        *(float4*)Ob       = o0;
        *(float4*)(Ob + 4) = o1;
    }
}

extern "C" void kernel_launch(void* const* d_in, const int* in_sizes, int n_in,
                              void* d_out, int out_size)
{
    const float* Q  = (const float*)d_in[0];
    const float* K  = (const float*)d_in[1];
    const float* V  = (const float*)d_in[2];
    const unsigned char* M = (const unsigned char*)d_in[3];
    const float* TS = (const float*)d_in[4];
    const float* LS = (const float*)d_in[5];

    float* out  = (float*)d_out;
    float* Osum = out;                                    // (B,H,L,DK)
    float* Pout = out + (size_t)NB * NH * LSEQ * DK;      // (B,H,L,L)

    prep_kernel<<<NBH * 32, NT>>>(K);

    cudaFuncSetAttribute(raa_kernel,
                         cudaFuncAttributeMaxDynamicSharedMemorySize,
                         (int)SMEM_BYTES);
    dim3 grid(LSEQ / TI, NBH);
    raa_kernel<<<grid, NT, SMEM_BYTES>>>(Q, V, M, TS, LS, Osum, Pout);
}

// round 5
// speedup vs baseline: 1.0028x; 1.0028x over previous
#include <cuda_runtime.h>

#define LSEQ 2048
#define DK   64
#define NH   8
#define NB   2
#define NBH  (NB*NH)
#define NT   256
#define TI   16
#define TJ   256      // phase-1 chunk width (cols)
#define TJ4  128      // phase-4 chunk height (j rows)

// K^T scratch: per bh, [DK][LSEQ]
__device__ float g_kt[(size_t)NBH * DK * LSEQ];

// smem layout (floats)
//  sS   : TI*LSEQ        = 32768
//  sAux : DK*TJ          = 16384   (K^T chunk / V chunk(8192) / reduce(1024))
//  sQ2  : TI*DK*2        =  2048   (Q pre-splatted into f32x2 pairs)
//  sRow : TI
#define SMEM_FLOATS (TI*LSEQ + DK*TJ + TI*DK*2 + TI)
#define SMEM_BYTES  (SMEM_FLOATS * sizeof(float))

#define FMA2(d,a,b,c) asm("fma.rn.f32x2 %0, %1, %2, %3;" : "=l"(d) : "l"(a), "l"(b), "l"(c))
#define ADD2(d,a,b)   asm("add.rn.f32x2 %0, %1, %2;"     : "=l"(d) : "l"(a), "l"(b))
#define SPLAT2(d,s)   asm("mov.b64 %0, {%1, %1};"        : "=l"(d) : "f"(s))
#define UNPK2(lo,hi,s) asm("mov.b64 {%0, %1}, %2;"       : "=f"(lo), "=f"(hi) : "l"(s))

// ---------------------------------------------------------------------------
// prep: transpose K[bh][j][kk] -> g_kt[bh][kk][j].  grid = NBH*32, 256 thr.
// ---------------------------------------------------------------------------
__global__ void prep_kernel(const float* __restrict__ K)
{
    __shared__ float sT[64 * 65];
    const int bh = blockIdx.x >> 5;
    const int jt = blockIdx.x & 31;          // 64-row j tile
    const int t  = threadIdx.x;
    const float* Kb = K + ((size_t)bh * LSEQ + jt * 64) * DK;

    #pragma unroll
    for (int it = 0; it < 4; it++) {
        int q   = t + it * NT;               // 0..1023 float4s
        int row = q >> 4;                    // j within tile
        int c4  = (q & 15) << 2;             // kk
        float4 v = *(const float4*)(Kb + (size_t)row * DK + c4);
        sT[(c4 + 0) * 65 + row] = v.x;
        sT[(c4 + 1) * 65 + row] = v.y;
        sT[(c4 + 2) * 65 + row] = v.z;
        sT[(c4 + 3) * 65 + row] = v.w;
    }
    __syncthreads();
    float* KTb = g_kt + (size_t)bh * DK * LSEQ + jt * 64;
    #pragma unroll
    for (int it = 0; it < 4; it++) {
        int q  = t + it * NT;
        int kk = q >> 4;
        int j4 = (q & 15) << 2;
        float4 v;
        v.x = sT[kk * 65 + j4 + 0];
        v.y = sT[kk * 65 + j4 + 1];
        v.z = sT[kk * 65 + j4 + 2];
        v.w = sT[kk * 65 + j4 + 3];
        *(float4*)(KTb + (size_t)kk * LSEQ + j4) = v;
    }
}

// ---------------------------------------------------------------------------
// Main fused kernel. grid = (LSEQ/TI, NBH), 256 threads, ~200KB smem.
// ---------------------------------------------------------------------------
__global__ __launch_bounds__(NT, 1)
void raa_kernel(const float* __restrict__ Q, const float* __restrict__ V,
                const unsigned char* __restrict__ M,
                const float* __restrict__ TS, const float* __restrict__ LS,
                float* __restrict__ Osum, float* __restrict__ Pout)
{
    extern __shared__ float sm[];
    float* sS   = sm;
    float* sAux = sS + TI * LSEQ;
    float* sQ2  = sAux + DK * TJ;
    float* sRow = sQ2 + TI * DK * 2;
    __shared__ int sFlag;

    const int t  = threadIdx.x;
    const int bh = blockIdx.y;
    const int b  = bh >> 3;
    const int i0 = blockIdx.x * TI;
    const float scale = 0.07216878364870323f;   // 1/sqrt(3*64)

    const float* Qb  = Q  + (size_t)bh * LSEQ * DK;
    const float* Vb  = V  + (size_t)bh * LSEQ * DK;
    const float* TSb = TS + ((size_t)bh * LSEQ + i0) * LSEQ;
    const float* LSb = LS + ((size_t)bh * LSEQ + i0) * LSEQ;
    const size_t moff = ((size_t)b * LSEQ + i0) * LSEQ;
    const float* KTb = g_kt + (size_t)bh * DK * LSEQ;

    // ---- mask dtype probe (thread 0) + Q splat load ----
    if (t == 0) {
        const int*   mi = (const int*)M;
        const float* mf = (const float*)M;
        bool okI = true, okF = true;
        for (int i = 0; i < 64; i++) {
            int   vi = mi[i];
            float vf = mf[i];
            if (vi != 0 && vi != 1)       okI = false;
            if (vf != 0.f && vf != 1.f)   okF = false;
        }
        sFlag = okI ? 1 : (okF ? 2 : 0);
    }
    {
        float4 qv = ((const float4*)(Qb + (size_t)i0 * DK))[t];
        int e = t * 4, row = e >> 6, kk = e & 63;
        float* d = sQ2 + ((size_t)row * DK + kk) * 2;
        d[0]=qv.x; d[1]=qv.x; d[2]=qv.y; d[3]=qv.y;
        d[4]=qv.z; d[5]=qv.z; d[6]=qv.w; d[7]=qv.w;
    }
    __syncthreads();
    const int flag = sFlag;

    // ---- Phase 1: S = (QK^T + tree + leaf)*scale, masked ----
    const int cq  = t & 63;         // col quad index (4 cols)
    const int ra  = (t >> 6) * 4;   // first of 4 rows
    const int jgq = cq * 4;

    for (int jc = 0; jc < LSEQ; jc += TJ) {
        __syncthreads();
        #pragma unroll
        for (int it = 0; it < 16; it++) {
            int idx = t + it * NT;              // 0..4095 float4s
            int kk  = idx >> 6;
            int c4  = (idx & 63) << 2;
            *(float4*)(sAux + kk * TJ + c4) =
                *(const float4*)(KTb + (size_t)kk * LSEQ + jc + c4);
        }
        // prefetch bias + mask for this thread's 4x4 tile
        const int jg = jc + jgq;
        float4 bias[4];
        unsigned mb = 0;
        #pragma unroll
        for (int r = 0; r < 4; r++) {
            float4 t4 = *(const float4*)(TSb + (size_t)(ra + r) * LSEQ + jg);
            float4 l4 = *(const float4*)(LSb + (size_t)(ra + r) * LSEQ + jg);
            bias[r].x = t4.x + l4.x; bias[r].y = t4.y + l4.y;
            bias[r].z = t4.z + l4.z; bias[r].w = t4.w + l4.w;
            unsigned m4;
            size_t eo = moff + (size_t)(ra + r) * LSEQ + jg;
            if (flag == 0) {
                unsigned w = *(const unsigned*)(M + eo);
                m4 = (w & 1u) | ((w >> 7) & 2u) | ((w >> 14) & 4u) | ((w >> 21) & 8u);
            } else if (flag == 1) {
                int4 w = *(const int4*)((const int*)M + eo);
                m4 = (w.x?1u:0u) | (w.y?2u:0u) | (w.z?4u:0u) | (w.w?8u:0u);
            } else {
                float4 w = *(const float4*)((const float*)M + eo);
                m4 = (w.x!=0.f?1u:0u) | (w.y!=0.f?2u:0u) | (w.z!=0.f?4u:0u) | (w.w!=0.f?8u:0u);
            }
            mb |= m4 << (r * 4);
        }
        __syncthreads();

        unsigned long long a0[4] = {0,0,0,0}, a1[4] = {0,0,0,0};
        #pragma unroll 8
        for (int kk = 0; kk < DK; kk += 2) {
            ulonglong2 kv0 = *(const ulonglong2*)(sAux + kk * TJ + jgq);
            ulonglong2 kv1 = *(const ulonglong2*)(sAux + (kk + 1) * TJ + jgq);
            #pragma unroll
            for (int r = 0; r < 4; r++) {
                ulonglong2 qp = *(const ulonglong2*)(sQ2 + ((size_t)(ra + r) * DK + kk) * 2);
                FMA2(a0[r], qp.x, kv0.x, a0[r]);
                FMA2(a1[r], qp.x, kv0.y, a1[r]);
                FMA2(a0[r], qp.y, kv1.x, a0[r]);
                FMA2(a1[r], qp.y, kv1.y, a1[r]);
            }
        }
        #pragma unroll
        for (int r = 0; r < 4; r++) {
            float lx, ly, hx, hy;
            UNPK2(lx, ly, a0[r]);
            UNPK2(hx, hy, a1[r]);
            float4 s;
            s.x = (mb >> (r*4)     & 1) ? -1e9f : (lx + bias[r].x) * scale;
            s.y = (mb >> (r*4 + 1) & 1) ? -1e9f : (ly + bias[r].y) * scale;
            s.z = (mb >> (r*4 + 2) & 1) ? -1e9f : (hx + bias[r].z) * scale;
            s.w = (mb >> (r*4 + 3) & 1) ? -1e9f : (hy + bias[r].w) * scale;
            *(float4*)(sS + (size_t)(ra + r) * LSEQ + jg) = s;
        }
    }
    __syncthreads();

    // ---- Phase 2: per-row max / exp / sum (16 threads per row, float4) ----
    {
        const int row = t >> 4;
        const int l16 = t & 15;
        float* sSr = sS + (size_t)row * LSEQ;
        float m = -3.4e38f;
        for (int k = l16; k < LSEQ/4; k += 16) {
            float4 v = ((const float4*)sSr)[k];
            m = fmaxf(m, fmaxf(fmaxf(v.x, v.y), fmaxf(v.z, v.w)));
        }
        #pragma unroll
        for (int k = 8; k >= 1; k >>= 1)
            m = fmaxf(m, __shfl_xor_sync(0xffffffffu, m, k));
        float sum = 0.f;
        for (int k = l16; k < LSEQ/4; k += 16) {
            float4 v = ((const float4*)sSr)[k];
            v.x = __expf(v.x - m); v.y = __expf(v.y - m);
            v.z = __expf(v.z - m); v.w = __expf(v.w - m);
            ((float4*)sSr)[k] = v;
            sum += (v.x + v.y) + (v.z + v.w);
        }
        #pragma unroll
        for (int k = 8; k >= 1; k >>= 1)
            sum += __shfl_xor_sync(0xffffffffu, sum, k);
        if (l16 == 0) sRow[row] = 1.0f / sum;
    }
    __syncthreads();

    // ---- Phase 3: normalize in smem + stream p_attn to gmem ----
    {
        float* Pb = Pout + ((size_t)bh * LSEQ + i0) * LSEQ;
        #pragma unroll
        for (int it = 0; it < (TI * LSEQ / 4) / NT; it++) {   // 32 iters
            int fidx = (t + it * NT) * 4;
            int r = fidx >> 11;
            float rinv = sRow[r];
            float4 p = *(float4*)(sS + fidx);
            p.x *= rinv; p.y *= rinv; p.z *= rinv; p.w *= rinv;
            *(float4*)(sS + fidx) = p;
            *(float4*)(Pb + fidx) = p;
        }
    }

    // ---- Phase 4: O = P V  (j split in halves; f32x2 dim pairs) ----
    const int prow = (t >> 3) & 15;   // output row
    const int oct  = t & 7;           // dim octet: dims oct*8 .. +7
    const int jh   = t >> 7;          // j-half
    unsigned long long accA0 = 0, accA1 = 0, accB0 = 0, accB1 = 0;

    for (int jc = 0; jc < LSEQ; jc += TJ4) {
        __syncthreads();
        #pragma unroll
        for (int it = 0; it < 8; it++) {
            int idx = t + it * NT;    // 0..2047 float4s of V chunk
            *(float4*)(sAux + idx * 4) =
                *(const float4*)(Vb + (size_t)jc * DK + idx * 4);
        }
        __syncthreads();
        const float* pr  = sS + (size_t)prow * LSEQ + jc + jh * 64;
        const float* vb0 = sAux + jh * 64 * DK + oct * 8;
        #pragma unroll 4
        for (int j4 = 0; j4 < 64; j4 += 4) {
            float4 p = *(const float4*)(pr + j4);
            #pragma unroll
            for (int u = 0; u < 4; u++) {
                float pv = (u == 0) ? p.x : (u == 1) ? p.y : (u == 2) ? p.z : p.w;
                unsigned long long ps;
                SPLAT2(ps, pv);
                const ulonglong2* v = (const ulonglong2*)(vb0 + (size_t)(j4 + u) * DK);
                ulonglong2 vA = v[0];
                ulonglong2 vB = v[1];
                FMA2(accA0, ps, vA.x, accA0);
                FMA2(accA1, ps, vA.y, accA1);
                FMA2(accB0, ps, vB.x, accB0);
                FMA2(accB1, ps, vB.y, accB1);
            }
        }
    }
    // cross-half reduce via sAux
    __syncthreads();
    if (jh == 1) {
        unsigned long long* red = (unsigned long long*)sAux + (size_t)(t - 128) * 4;
        red[0] = accA0; red[1] = accA1; red[2] = accB0; red[3] = accB1;
    }
    __syncthreads();
    if (jh == 0) {
        const unsigned long long* red = (const unsigned long long*)sAux + (size_t)t * 4;
        ADD2(accA0, accA0, red[0]);
        ADD2(accA1, accA1, red[1]);
        ADD2(accB0, accB0, red[2]);
        ADD2(accB1, accB1, red[3]);
        float4 o0, o1;
        UNPK2(o0.x, o0.y, accA0); UNPK2(o0.z, o0.w, accA1);
        UNPK2(o1.x, o1.y, accB0); UNPK2(o1.z, o1.w, accB1);
        float* Ob = Osum + ((size_t)bh * LSEQ + i0 + prow) * DK + oct * 8;
        *(float4*)Ob       = o0;
        *(float4*)(Ob + 4) = o1;
    }
}

extern "C" void kernel_launch(void* const* d_in, const int* in_sizes, int n_in,
                              void* d_out, int out_size)
{
    const float* Q  = (const float*)d_in[0];
    const float* K  = (const float*)d_in[1];
    const float* V  = (const float*)d_in[2];
    const unsigned char* M = (const unsigned char*)d_in[3];
    const float* TS = (const float*)d_in[4];
    const float* LS = (const float*)d_in[5];

    float* out  = (float*)d_out;
    float* Osum = out;                                    // (B,H,L,DK)
    float* Pout = out + (size_t)NB * NH * LSEQ * DK;      // (B,H,L,L)

    prep_kernel<<<NBH * 32, NT>>>(K);

    cudaFuncSetAttribute(raa_kernel,
                         cudaFuncAttributeMaxDynamicSharedMemorySize,
                         (int)SMEM_BYTES);
    dim3 grid(LSEQ / TI, NBH);
    raa_kernel<<<grid, NT, SMEM_BYTES>>>(Q, V, M, TS, LS, Osum, Pout);
}

// round 7
// speedup vs baseline: 1.4754x; 1.4713x over previous
#include <cuda_runtime.h>
#include <cuda_bf16.h>
#include <cstdint>

#define LSEQ 2048
#define NBH  16
#define SCALE 0.07216878364870323f   // 1/sqrt(3*64)
#define SSTR 2052                    // floats per sS row (pad 4)
#define KSTR 68                      // words per K-chunk row (64 + pad 4)
#define VSTR 260                     // words per V^T row (256 + pad 4)

// dynamic smem byte offsets
#define OFF_KV 131328                // sS = 16*2052*4
#define OFF_Q  200960                // KV = 256*68*4 = 69632
#define SMEM_BYTES 205312            // Q  = 16*68*4  = 4352

__device__ __forceinline__ uint32_t packsplit(float x) {
    __nv_bfloat16 h = __float2bfloat16(x);
    float hf = __bfloat162float(h);
    __nv_bfloat16 l = __float2bfloat16(x - hf);
    unsigned short hs = *(unsigned short*)&h, ls = *(unsigned short*)&l;
    return (uint32_t)hs | ((uint32_t)ls << 16);
}
#define PHI(w0,w1) __byte_perm((w0), (w1), 0x5410)   // low halves  -> hi pair
#define PLO(w0,w1) __byte_perm((w0), (w1), 0x7632)   // high halves -> lo pair

#define MMA(c, a0,a1,a2,a3, b0,b1) \
  asm volatile("mma.sync.aligned.m16n8k16.row.col.f32.bf16.bf16.f32 " \
    "{%0,%1,%2,%3}, {%4,%5,%6,%7}, {%8,%9}, {%0,%1,%2,%3};" \
    : "+f"((c)[0]), "+f"((c)[1]), "+f"((c)[2]), "+f"((c)[3]) \
    : "r"(a0), "r"(a1), "r"(a2), "r"(a3), "r"(b0), "r"(b1))

__global__ __launch_bounds__(256, 1)
void raa_kernel(const float* __restrict__ Q, const float* __restrict__ K,
                const float* __restrict__ V, const unsigned char* __restrict__ M,
                const float* __restrict__ TS, const float* __restrict__ LS,
                float* __restrict__ O, float* __restrict__ P)
{
    extern __shared__ char smem[];
    float*    sS  = (float*)smem;
    uint32_t* sSw = (uint32_t*)smem;
    uint32_t* sKV = (uint32_t*)(smem + OFF_KV);
    uint32_t* sQ  = (uint32_t*)(smem + OFF_Q);
    __shared__ float sRow[16];
    __shared__ int   sFlag;

    const int t = threadIdx.x, w = t >> 5, lane = t & 31;
    const int g = lane >> 2, tig = lane & 3;
    const int bh = blockIdx.y, i0 = blockIdx.x * 16;

    // ---- mask dtype probe (flag: 0=bool, 1=int32, 2=float32) ----
    if (t == 0) {
        const int* mi = (const int*)M; const float* mf = (const float*)M;
        bool okI = true, okF = true;
        for (int i = 0; i < 64; i++) {
            int vi = mi[i]; float vf = mf[i];
            if (vi != 0 && vi != 1)     okI = false;
            if (vf != 0.f && vf != 1.f) okF = false;
        }
        sFlag = okI ? 1 : (okF ? 2 : 0);
    }
    // ---- stage Q packed (16 x 64) ----
    {
        float4 qv = ((const float4*)(Q + ((size_t)bh * LSEQ + i0) * 64))[t];
        int row = t >> 4, k4 = (t & 15) * 4;
        uint4 pw = make_uint4(packsplit(qv.x), packsplit(qv.y), packsplit(qv.z), packsplit(qv.w));
        *(uint4*)(sQ + row * KSTR + k4) = pw;
    }
    __syncthreads();
    const int flag = sFlag;

    // ---- A-frags for Q (held in regs for all of phase 1) ----
    uint32_t qh[16], ql[16];
    #pragma unroll
    for (int ks = 0; ks < 4; ks++) {
        int c0 = ks * 16 + 2 * tig;
        uint32_t w00 = sQ[g * KSTR + c0],       w01 = sQ[g * KSTR + c0 + 1];
        uint32_t w10 = sQ[(g + 8) * KSTR + c0], w11 = sQ[(g + 8) * KSTR + c0 + 1];
        uint32_t w20 = sQ[g * KSTR + c0 + 8],   w21 = sQ[g * KSTR + c0 + 9];
        uint32_t w30 = sQ[(g + 8) * KSTR + c0 + 8], w31 = sQ[(g + 8) * KSTR + c0 + 9];
        qh[ks*4+0] = PHI(w00, w01); ql[ks*4+0] = PLO(w00, w01);
        qh[ks*4+1] = PHI(w10, w11); ql[ks*4+1] = PLO(w10, w11);
        qh[ks*4+2] = PHI(w20, w21); ql[ks*4+2] = PLO(w20, w21);
        qh[ks*4+3] = PHI(w30, w31); ql[ks*4+3] = PLO(w30, w31);
    }

    // ---- Phase 1: S = Q K^T (raw) via HMMA ----
    const float* Kb = K + (size_t)bh * LSEQ * 64;
    for (int jc = 0; jc < LSEQ; jc += 256) {
        __syncthreads();
        #pragma unroll
        for (int it = 0; it < 16; it++) {
            int idx = t + it * 256;                   // 0..4095 float4s
            int j = idx >> 4, k4 = (idx & 15) * 4;
            float4 kv = *(const float4*)(Kb + (size_t)(jc + j) * 64 + k4);
            uint4 pw = make_uint4(packsplit(kv.x), packsplit(kv.y), packsplit(kv.z), packsplit(kv.w));
            *(uint4*)(sKV + j * KSTR + k4) = pw;
        }
        __syncthreads();
        float acc[4][4];
        #pragma unroll
        for (int nt = 0; nt < 4; nt++)
            acc[nt][0] = acc[nt][1] = acc[nt][2] = acc[nt][3] = 0.f;
        const int jb = 32 * w;
        #pragma unroll
        for (int ks = 0; ks < 4; ks++) {
            #pragma unroll
            for (int nt = 0; nt < 4; nt++) {
                int jrow = jb + 8 * nt + g;
                int kw = ks * 16 + 2 * tig;
                uint32_t w0 = sKV[jrow * KSTR + kw],     w1 = sKV[jrow * KSTR + kw + 1];
                uint32_t w2 = sKV[jrow * KSTR + kw + 8], w3 = sKV[jrow * KSTR + kw + 9];
                uint32_t bh0 = PHI(w0, w1), bl0 = PLO(w0, w1);
                uint32_t bh1 = PHI(w2, w3), bl1 = PLO(w2, w3);
                MMA(acc[nt], qh[ks*4], qh[ks*4+1], qh[ks*4+2], qh[ks*4+3], bh0, bh1);
                MMA(acc[nt], qh[ks*4], qh[ks*4+1], qh[ks*4+2], qh[ks*4+3], bl0, bl1);
                MMA(acc[nt], ql[ks*4], ql[ks*4+1], ql[ks*4+2], ql[ks*4+3], bh0, bh1);
            }
        }
        #pragma unroll
        for (int nt = 0; nt < 4; nt++) {
            int col = jc + jb + 8 * nt + 2 * tig;
            *(float2*)(sS + (size_t)g * SSTR + col)       = make_float2(acc[nt][0], acc[nt][1]);
            *(float2*)(sS + (size_t)(g + 8) * SSTR + col) = make_float2(acc[nt][2], acc[nt][3]);
        }
    }
    __syncthreads();

    // ---- Phase 2: bias + mask + softmax stats (16 lanes per row) ----
    {
        const int row = t >> 4, l16 = t & 15;
        float* sSr = sS + (size_t)row * SSTR;
        const size_t grow = (size_t)bh * LSEQ + i0 + row;
        const float* tsr = TS + grow * LSEQ;
        const float* lsr = LS + grow * LSEQ;
        const size_t mrow = ((size_t)(bh >> 3) * LSEQ + i0 + row) * LSEQ;
        float mx = -3.4e38f;
        for (int c4 = l16; c4 < 512; c4 += 16) {
            float4 s = ((const float4*)sSr)[c4];
            float4 t4 = *(const float4*)(tsr + c4 * 4);
            float4 l4 = *(const float4*)(lsr + c4 * 4);
            unsigned mb;
            if (flag == 1) { int4 v = *(const int4*)((const int*)M + mrow + c4 * 4);
                mb = (v.x?1u:0)|(v.y?2u:0)|(v.z?4u:0)|(v.w?8u:0); }
            else if (flag == 0) { uchar4 v = *(const uchar4*)(M + mrow + c4 * 4);
                mb = (v.x?1u:0)|(v.y?2u:0)|(v.z?4u:0)|(v.w?8u:0); }
            else { float4 v = *(const float4*)((const float*)M + mrow + c4 * 4);
                mb = (v.x!=0.f?1u:0)|(v.y!=0.f?2u:0)|(v.z!=0.f?4u:0)|(v.w!=0.f?8u:0); }
            s.x = (mb & 1u) ? -1e9f : (s.x + t4.x + l4.x) * SCALE;
            s.y = (mb & 2u) ? -1e9f : (s.y + t4.y + l4.y) * SCALE;
            s.z = (mb & 4u) ? -1e9f : (s.z + t4.z + l4.z) * SCALE;
            s.w = (mb & 8u) ? -1e9f : (s.w + t4.w + l4.w) * SCALE;
            ((float4*)sSr)[c4] = s;
            mx = fmaxf(mx, fmaxf(fmaxf(s.x, s.y), fmaxf(s.z, s.w)));
        }
        #pragma unroll
        for (int k = 8; k >= 1; k >>= 1)
            mx = fmaxf(mx, __shfl_xor_sync(0xffffffffu, mx, k));
        float sum = 0.f;
        for (int c4 = l16; c4 < 512; c4 += 16) {
            float4 s = ((const float4*)sSr)[c4];
            s.x = __expf(s.x - mx); s.y = __expf(s.y - mx);
            s.z = __expf(s.z - mx); s.w = __expf(s.w - mx);
            ((float4*)sSr)[c4] = s;
            sum += (s.x + s.y) + (s.z + s.w);
        }
        #pragma unroll
        for (int k = 8; k >= 1; k >>= 1)
            sum += __shfl_xor_sync(0xffffffffu, sum, k);
        if (l16 == 0) sRow[row] = 1.0f / sum;
    }
    __syncthreads();

    // ---- Phase 3: normalize, write P, repack S as bf16 hi/lo words ----
    {
        float* Pb = P + ((size_t)bh * LSEQ + i0) * LSEQ;
        #pragma unroll
        for (int it = 0; it < 32; it++) {
            int task = t + it * 256;          // 0..8191 float4s
            int r = task >> 9, c4 = task & 511;
            float rinv = sRow[r];
            float4 e = ((const float4*)(sS + (size_t)r * SSTR))[c4];
            e.x *= rinv; e.y *= rinv; e.z *= rinv; e.w *= rinv;
            *(float4*)(Pb + (size_t)r * LSEQ + c4 * 4) = e;
            uint4 pw = make_uint4(packsplit(e.x), packsplit(e.y), packsplit(e.z), packsplit(e.w));
            ((uint4*)(sSw + (size_t)r * SSTR))[c4] = pw;
        }
    }

    // ---- Phase 4: O = P V via HMMA (warp w owns j-range per chunk) ----
    float oc[8][4];
    #pragma unroll
    for (int nt = 0; nt < 8; nt++)
        oc[nt][0] = oc[nt][1] = oc[nt][2] = oc[nt][3] = 0.f;
    const float* Vb = V + (size_t)bh * LSEQ * 64;
    for (int jc = 0; jc < LSEQ; jc += 256) {
        __syncthreads();
        #pragma unroll
        for (int it = 0; it < 16; it++) {
            int idx = t + it * 256;                 // 0..4095 float4s
            int d4 = idx & 15, j = idx >> 4;
            float4 vv = *(const float4*)(Vb + (size_t)(jc + j) * 64 + d4 * 4);
            uint32_t p0 = packsplit(vv.x), p1 = packsplit(vv.y);
            uint32_t p2 = packsplit(vv.z), p3 = packsplit(vv.w);
            sKV[(4*d4+0) * VSTR + j] = p0; sKV[(4*d4+1) * VSTR + j] = p1;
            sKV[(4*d4+2) * VSTR + j] = p2; sKV[(4*d4+3) * VSTR + j] = p3;
        }
        __syncthreads();
        #pragma unroll
        for (int ksl = 0; ksl < 2; ksl++) {
            int jl = (2 * w + ksl) * 16;            // j-local base of this k-step
            // A-frags from packed P in sS
            int ac = jc + jl + 2 * tig;
            uint32_t w00 = sSw[(size_t)g * SSTR + ac],       w01 = sSw[(size_t)g * SSTR + ac + 1];
            uint32_t w10 = sSw[(size_t)(g+8) * SSTR + ac],   w11 = sSw[(size_t)(g+8) * SSTR + ac + 1];
            uint32_t w20 = sSw[(size_t)g * SSTR + ac + 8],   w21 = sSw[(size_t)g * SSTR + ac + 9];
            uint32_t w30 = sSw[(size_t)(g+8) * SSTR + ac + 8], w31 = sSw[(size_t)(g+8) * SSTR + ac + 9];
            uint32_t ah0 = PHI(w00,w01), ah1 = PHI(w10,w11), ah2 = PHI(w20,w21), ah3 = PHI(w30,w31);
            uint32_t al0 = PLO(w00,w01), al1 = PLO(w10,w11), al2 = PLO(w20,w21), al3 = PLO(w30,w31);
            int jb2 = jl + 2 * tig;
            #pragma unroll
            for (int nt = 0; nt < 8; nt++) {
                int dim = 8 * nt + g;
                uint32_t v0 = sKV[dim * VSTR + jb2],     v1 = sKV[dim * VSTR + jb2 + 1];
                uint32_t v2 = sKV[dim * VSTR + jb2 + 8], v3 = sKV[dim * VSTR + jb2 + 9];
                uint32_t bh0 = PHI(v0, v1), bl0 = PLO(v0, v1);
                uint32_t bh1 = PHI(v2, v3), bl1 = PLO(v2, v3);
                MMA(oc[nt], ah0, ah1, ah2, ah3, bh0, bh1);
                MMA(oc[nt], ah0, ah1, ah2, ah3, bl0, bl1);
                MMA(oc[nt], al0, al1, al2, al3, bh0, bh1);
            }
        }
    }
    // cross-warp reduce: partials in sS (free now)
    __syncthreads();
    {
        float* sPart = sS;
        #pragma unroll
        for (int nt = 0; nt < 8; nt++) {
            int dimb = 8 * nt + 2 * tig;
            *(float2*)(sPart + ((size_t)(w * 16 + g) * 64) + dimb)     = make_float2(oc[nt][0], oc[nt][1]);
            *(float2*)(sPart + ((size_t)(w * 16 + g + 8) * 64) + dimb) = make_float2(oc[nt][2], oc[nt][3]);
        }
    }
    __syncthreads();
    {
        int row = t >> 4, d4 = (t & 15) * 4;
        float4 o = make_float4(0.f, 0.f, 0.f, 0.f);
        #pragma unroll
        for (int w8 = 0; w8 < 8; w8++) {
            float4 p4 = *(const float4*)(sS + ((size_t)(w8 * 16 + row) * 64) + d4);
            o.x += p4.x; o.y += p4.y; o.z += p4.z; o.w += p4.w;
        }
        *(float4*)(O + ((size_t)bh * LSEQ + i0 + row) * 64 + d4) = o;
    }
}

extern "C" void kernel_launch(void* const* d_in, const int* in_sizes, int n_in,
                              void* d_out, int out_size)
{
    const float* Q  = (const float*)d_in[0];
    const float* K  = (const float*)d_in[1];
    const float* V  = (const float*)d_in[2];
    const unsigned char* M = (const unsigned char*)d_in[3];
    const float* TS = (const float*)d_in[4];
    const float* LS = (const float*)d_in[5];
    float* out  = (float*)d_out;
    float* O = out;
    float* P = out + (size_t)NBH * LSEQ * 64;

    cudaFuncSetAttribute(raa_kernel, cudaFuncAttributeMaxDynamicSharedMemorySize, SMEM_BYTES);
    dim3 grid(LSEQ / 16, NBH);
    raa_kernel<<<grid, 256, SMEM_BYTES>>>(Q, K, V, M, TS, LS, O, P);
}

// round 8
// speedup vs baseline: 2.3750x; 1.6098x over previous
#include <cuda_runtime.h>
#include <cuda_bf16.h>
#include <cstdint>

#define LSEQ 2048
#define NBH  16
#define NT   512
#define SCALE 0.07216878364870323f   // 1/sqrt(3*64)
#define SSTR 2052
#define KSTR 68
#define VSTR 260

#define OFF_KV 131328                // sS = 16*2052*4
#define OFF_Q  200960                // KV = 256*68*4 = 69632
#define SMEM_BYTES 205312            // Q  = 16*68*4  = 4352

// packed (bf16_hi | bf16_lo<<16) scratch
__device__ uint32_t g_qp[(size_t)NBH * LSEQ * 64];
__device__ uint32_t g_kp[(size_t)NBH * LSEQ * 64];
__device__ uint32_t g_vp[(size_t)NBH * 64 * LSEQ];   // transposed [bh][dim][j]

__device__ __forceinline__ uint32_t packsplit(float x) {
    __nv_bfloat16 h = __float2bfloat16(x);
    float hf = __bfloat162float(h);
    __nv_bfloat16 l = __float2bfloat16(x - hf);
    unsigned short hs = *(unsigned short*)&h, ls = *(unsigned short*)&l;
    return (uint32_t)hs | ((uint32_t)ls << 16);
}
#define PHI(w0,w1) __byte_perm((w0), (w1), 0x5410)
#define PLO(w0,w1) __byte_perm((w0), (w1), 0x7632)

#define MMA(c, a0,a1,a2,a3, b0,b1) \
  asm volatile("mma.sync.aligned.m16n8k16.row.col.f32.bf16.bf16.f32 " \
    "{%0,%1,%2,%3}, {%4,%5,%6,%7}, {%8,%9}, {%0,%1,%2,%3};" \
    : "+f"((c)[0]), "+f"((c)[1]), "+f"((c)[2]), "+f"((c)[3]) \
    : "r"(a0), "r"(a1), "r"(a2), "r"(a3), "r"(b0), "r"(b1))

// ---------------- prep: pack Q/K; transpose+pack V ----------------
__global__ void prep_kernel(const float* __restrict__ Q, const float* __restrict__ K,
                            const float* __restrict__ V)
{
    const int t = threadIdx.x;
    if (blockIdx.x < 1024) {
        #pragma unroll
        for (int i = 0; i < 2; i++) {
            size_t idx4 = (size_t)blockIdx.x * 512 + t + (size_t)i * 256;
            float4 q = ((const float4*)Q)[idx4];
            ((uint4*)g_qp)[idx4] = make_uint4(packsplit(q.x), packsplit(q.y),
                                             packsplit(q.z), packsplit(q.w));
            float4 k = ((const float4*)K)[idx4];
            ((uint4*)g_kp)[idx4] = make_uint4(packsplit(k.x), packsplit(k.y),
                                             packsplit(k.z), packsplit(k.w));
        }
    } else {
        __shared__ float sT[64 * 65];
        int bi = blockIdx.x - 1024, bh = bi >> 5, jt = bi & 31;
        const float* Vb = V + ((size_t)bh * LSEQ + jt * 64) * 64;
        #pragma unroll
        for (int i = 0; i < 4; i++) {
            int q = t + i * 256, j = q >> 4, n4 = (q & 15) * 4;
            float4 v = *(const float4*)(Vb + (size_t)j * 64 + n4);
            sT[(n4+0)*65 + j] = v.x; sT[(n4+1)*65 + j] = v.y;
            sT[(n4+2)*65 + j] = v.z; sT[(n4+3)*65 + j] = v.w;
        }
        __syncthreads();
        #pragma unroll
        for (int i = 0; i < 4; i++) {
            int q = t + i * 256, dim = q >> 4, j4 = (q & 15) * 4;
            uint4 pw = make_uint4(packsplit(sT[dim*65 + j4]),
                                  packsplit(sT[dim*65 + j4 + 1]),
                                  packsplit(sT[dim*65 + j4 + 2]),
                                  packsplit(sT[dim*65 + j4 + 3]));
            *(uint4*)(g_vp + ((size_t)bh * 64 + dim) * LSEQ + jt * 64 + j4) = pw;
        }
    }
}

// ---------------- main fused kernel ----------------
__global__ __launch_bounds__(NT, 1)
void raa_kernel(const unsigned char* __restrict__ M,
                const float* __restrict__ TS, const float* __restrict__ LS,
                float* __restrict__ O, float* __restrict__ P)
{
    extern __shared__ char smem[];
    float*    sS  = (float*)smem;
    uint32_t* sSw = (uint32_t*)smem;
    uint32_t* sKV = (uint32_t*)(smem + OFF_KV);
    uint32_t* sQ  = (uint32_t*)(smem + OFF_Q);
    __shared__ float sRow[16];
    __shared__ int   sFlag;

    const int t = threadIdx.x, w = t >> 5, lane = t & 31;
    const int g = lane >> 2, tig = lane & 3;
    const int bh = blockIdx.y, i0 = blockIdx.x * 16;

    if (t == 0) {
        const int* mi = (const int*)M; const float* mf = (const float*)M;
        bool okI = true, okF = true;
        for (int i = 0; i < 64; i++) {
            int vi = mi[i]; float vf = mf[i];
            if (vi != 0 && vi != 1)     okI = false;
            if (vf != 0.f && vf != 1.f) okF = false;
        }
        sFlag = okI ? 1 : (okF ? 2 : 0);
    }
    if (t < 256) {
        int row = t >> 4, k4 = (t & 15) * 4;
        uint4 pw = *((const uint4*)(g_qp + ((size_t)bh * LSEQ + i0) * 64) + t);
        *(uint4*)(sQ + row * KSTR + k4) = pw;
    }
    __syncthreads();
    const int flag = sFlag;

    // A-frags for Q, resident through phase 1
    uint32_t qh[16], ql[16];
    #pragma unroll
    for (int ks = 0; ks < 4; ks++) {
        int c0 = ks * 16 + 2 * tig;
        uint32_t w00 = sQ[g * KSTR + c0],           w01 = sQ[g * KSTR + c0 + 1];
        uint32_t w10 = sQ[(g + 8) * KSTR + c0],     w11 = sQ[(g + 8) * KSTR + c0 + 1];
        uint32_t w20 = sQ[g * KSTR + c0 + 8],       w21 = sQ[g * KSTR + c0 + 9];
        uint32_t w30 = sQ[(g + 8) * KSTR + c0 + 8], w31 = sQ[(g + 8) * KSTR + c0 + 9];
        qh[ks*4+0] = PHI(w00, w01); ql[ks*4+0] = PLO(w00, w01);
        qh[ks*4+1] = PHI(w10, w11); ql[ks*4+1] = PLO(w10, w11);
        qh[ks*4+2] = PHI(w20, w21); ql[ks*4+2] = PLO(w20, w21);
        qh[ks*4+3] = PHI(w30, w31); ql[ks*4+3] = PLO(w30, w31);
    }

    // ---- Phase 1: S = Q K^T ----
    const uint4* Kp = (const uint4*)(g_kp + (size_t)bh * LSEQ * 64);
    for (int jc = 0; jc < LSEQ; jc += 256) {
        __syncthreads();
        #pragma unroll
        for (int it = 0; it < 8; it++) {
            int idx = t + it * NT;                 // 0..4095 uint4s
            int j = idx >> 4, k4 = (idx & 15) * 4;
            *(uint4*)(sKV + j * KSTR + k4) = Kp[((size_t)(jc + j) << 4) + (idx & 15)];
        }
        __syncthreads();
        float acc[2][4];
        #pragma unroll
        for (int nt = 0; nt < 2; nt++)
            acc[nt][0] = acc[nt][1] = acc[nt][2] = acc[nt][3] = 0.f;
        const int jb = 16 * w;
        #pragma unroll
        for (int ks = 0; ks < 4; ks++) {
            #pragma unroll
            for (int nt = 0; nt < 2; nt++) {
                int jrow = jb + 8 * nt + g;
                int kw = ks * 16 + 2 * tig;
                uint32_t w0 = sKV[jrow * KSTR + kw],     w1 = sKV[jrow * KSTR + kw + 1];
                uint32_t w2 = sKV[jrow * KSTR + kw + 8], w3 = sKV[jrow * KSTR + kw + 9];
                uint32_t bh0 = PHI(w0, w1), bl0 = PLO(w0, w1);
                uint32_t bh1 = PHI(w2, w3), bl1 = PLO(w2, w3);
                MMA(acc[nt], qh[ks*4], qh[ks*4+1], qh[ks*4+2], qh[ks*4+3], bh0, bh1);
                MMA(acc[nt], qh[ks*4], qh[ks*4+1], qh[ks*4+2], qh[ks*4+3], bl0, bl1);
                MMA(acc[nt], ql[ks*4], ql[ks*4+1], ql[ks*4+2], ql[ks*4+3], bh0, bh1);
            }
        }
        #pragma unroll
        for (int nt = 0; nt < 2; nt++) {
            int col = jc + jb + 8 * nt + 2 * tig;
            *(float2*)(sS + (size_t)g * SSTR + col)       = make_float2(acc[nt][0], acc[nt][1]);
            *(float2*)(sS + (size_t)(g + 8) * SSTR + col) = make_float2(acc[nt][2], acc[nt][3]);
        }
    }
    __syncthreads();

    // ---- Phase 2: bias + mask + softmax stats (warp w owns row w) ----
    {
        const int row = w;
        float* sSr = sS + (size_t)row * SSTR;
        const size_t grow = (size_t)bh * LSEQ + i0 + row;
        const float* tsr = TS + grow * LSEQ;
        const float* lsr = LS + grow * LSEQ;
        const size_t mrow = ((size_t)(bh >> 3) * LSEQ + i0 + row) * LSEQ;
        float mx = -3.4e38f;
        for (int c4 = lane; c4 < 512; c4 += 32) {
            float4 s = ((const float4*)sSr)[c4];
            float4 t4 = *(const float4*)(tsr + c4 * 4);
            float4 l4 = *(const float4*)(lsr + c4 * 4);
            unsigned mb;
            if (flag == 1) { int4 v = *(const int4*)((const int*)M + mrow + c4 * 4);
                mb = (v.x?1u:0)|(v.y?2u:0)|(v.z?4u:0)|(v.w?8u:0); }
            else if (flag == 0) { uchar4 v = *(const uchar4*)(M + mrow + c4 * 4);
                mb = (v.x?1u:0)|(v.y?2u:0)|(v.z?4u:0)|(v.w?8u:0); }
            else { float4 v = *(const float4*)((const float*)M + mrow + c4 * 4);
                mb = (v.x!=0.f?1u:0)|(v.y!=0.f?2u:0)|(v.z!=0.f?4u:0)|(v.w!=0.f?8u:0); }
            s.x = (mb & 1u) ? -1e9f : (s.x + t4.x + l4.x) * SCALE;
            s.y = (mb & 2u) ? -1e9f : (s.y + t4.y + l4.y) * SCALE;
            s.z = (mb & 4u) ? -1e9f : (s.z + t4.z + l4.z) * SCALE;
            s.w = (mb & 8u) ? -1e9f : (s.w + t4.w + l4.w) * SCALE;
            ((float4*)sSr)[c4] = s;
            mx = fmaxf(mx, fmaxf(fmaxf(s.x, s.y), fmaxf(s.z, s.w)));
        }
        #pragma unroll
        for (int k = 16; k >= 1; k >>= 1)
            mx = fmaxf(mx, __shfl_xor_sync(0xffffffffu, mx, k));
        float sum = 0.f;
        for (int c4 = lane; c4 < 512; c4 += 32) {
            float4 s = ((const float4*)sSr)[c4];
            s.x = __expf(s.x - mx); s.y = __expf(s.y - mx);
            s.z = __expf(s.z - mx); s.w = __expf(s.w - mx);
            ((float4*)sSr)[c4] = s;
            sum += (s.x + s.y) + (s.z + s.w);
        }
        #pragma unroll
        for (int k = 16; k >= 1; k >>= 1)
            sum += __shfl_xor_sync(0xffffffffu, sum, k);
        if (lane == 0) sRow[row] = 1.0f / sum;
    }
    __syncthreads();

    // ---- Phase 3: normalize, write P, repack packed bf16 ----
    {
        float* Pb = P + ((size_t)bh * LSEQ + i0) * LSEQ;
        #pragma unroll
        for (int it = 0; it < 16; it++) {
            int task = t + it * NT;           // 0..8191 float4s
            int r = task >> 9, c4 = task & 511;
            float rinv = sRow[r];
            float4 e = ((const float4*)(sS + (size_t)r * SSTR))[c4];
            e.x *= rinv; e.y *= rinv; e.z *= rinv; e.w *= rinv;
            *(float4*)(Pb + (size_t)r * LSEQ + c4 * 4) = e;
            uint4 pw = make_uint4(packsplit(e.x), packsplit(e.y), packsplit(e.z), packsplit(e.w));
            ((uint4*)(sSw + (size_t)r * SSTR))[c4] = pw;
        }
    }

    // ---- Phase 4: O = P V ----
    float oc[8][4];
    #pragma unroll
    for (int nt = 0; nt < 8; nt++)
        oc[nt][0] = oc[nt][1] = oc[nt][2] = oc[nt][3] = 0.f;
    const uint4* Vp = (const uint4*)(g_vp + (size_t)bh * 64 * LSEQ);
    for (int jc = 0; jc < LSEQ; jc += 256) {
        __syncthreads();
        #pragma unroll
        for (int it = 0; it < 8; it++) {
            int idx = t + it * NT;                   // 0..4095 uint4s
            int dim = idx >> 6, u4 = idx & 63;
            *(uint4*)(sKV + dim * VSTR + u4 * 4) = Vp[(size_t)dim * 512 + (jc >> 2) + u4];
        }
        __syncthreads();
        const int jl = 16 * w;
        int ac = jc + jl + 2 * tig;
        uint32_t w00 = sSw[(size_t)g * SSTR + ac],         w01 = sSw[(size_t)g * SSTR + ac + 1];
        uint32_t w10 = sSw[(size_t)(g+8) * SSTR + ac],     w11 = sSw[(size_t)(g+8) * SSTR + ac + 1];
        uint32_t w20 = sSw[(size_t)g * SSTR + ac + 8],     w21 = sSw[(size_t)g * SSTR + ac + 9];
        uint32_t w30 = sSw[(size_t)(g+8) * SSTR + ac + 8], w31 = sSw[(size_t)(g+8) * SSTR + ac + 9];
        uint32_t ah0 = PHI(w00,w01), ah1 = PHI(w10,w11), ah2 = PHI(w20,w21), ah3 = PHI(w30,w31);
        uint32_t al0 = PLO(w00,w01), al1 = PLO(w10,w11), al2 = PLO(w20,w21), al3 = PLO(w30,w31);
        int jb2 = jl + 2 * tig;
        #pragma unroll
        for (int nt = 0; nt < 8; nt++) {
            int dim = 8 * nt + g;
            uint32_t v0 = sKV[dim * VSTR + jb2],     v1 = sKV[dim * VSTR + jb2 + 1];
            uint32_t v2 = sKV[dim * VSTR + jb2 + 8], v3 = sKV[dim * VSTR + jb2 + 9];
            uint32_t bh0 = PHI(v0, v1), bl0 = PLO(v0, v1);
            uint32_t bh1 = PHI(v2, v3), bl1 = PLO(v2, v3);
            MMA(oc[nt], ah0, ah1, ah2, ah3, bh0, bh1);
            MMA(oc[nt], ah0, ah1, ah2, ah3, bl0, bl1);
            MMA(oc[nt], al0, al1, al2, al3, bh0, bh1);
        }
    }
    __syncthreads();
    {
        #pragma unroll
        for (int nt = 0; nt < 8; nt++) {
            int dimb = 8 * nt + 2 * tig;
            *(float2*)(sS + ((size_t)(w * 16 + g) * 64) + dimb)     = make_float2(oc[nt][0], oc[nt][1]);
            *(float2*)(sS + ((size_t)(w * 16 + g + 8) * 64) + dimb) = make_float2(oc[nt][2], oc[nt][3]);
        }
    }
    __syncthreads();
    {
        int row = t >> 5, d = (t & 31) * 2;
        float2 o = make_float2(0.f, 0.f);
        #pragma unroll
        for (int w8 = 0; w8 < 16; w8++) {
            float2 p2 = *(const float2*)(sS + ((size_t)(w8 * 16 + row) * 64) + d);
            o.x += p2.x; o.y += p2.y;
        }
        *(float2*)(O + ((size_t)bh * LSEQ + i0 + row) * 64 + d) = o;
    }
}

extern "C" void kernel_launch(void* const* d_in, const int* in_sizes, int n_in,
                              void* d_out, int out_size)
{
    const float* Q  = (const float*)d_in[0];
    const float* K  = (const float*)d_in[1];
    const float* V  = (const float*)d_in[2];
    const unsigned char* M = (const unsigned char*)d_in[3];
    const float* TS = (const float*)d_in[4];
    const float* LS = (const float*)d_in[5];
    float* out = (float*)d_out;
    float* O = out;
    float* P = out + (size_t)NBH * LSEQ * 64;

    prep_kernel<<<1536, 256>>>(Q, K, V);
    cudaFuncSetAttribute(raa_kernel, cudaFuncAttributeMaxDynamicSharedMemorySize, SMEM_BYTES);
    dim3 grid(LSEQ / 16, NBH);
    raa_kernel<<<grid, NT, SMEM_BYTES>>>(M, TS, LS, O, P);
}